// round 14
// baseline (speedup 1.0000x reference)
#include <cuda_runtime.h>
#include <cuda_bf16.h>
#include <math.h>
#include <stdint.h>

// Problem constants
#define NTOK   2048
#define DD     1024
#define HH     2048
#define EE     8
#define NROWS  4096        // NTOK * topk(2) slot-rows

// Padded smem row strides (u32): %32 == 8 -> conflict-free fragment banks
#define APAD 136
#define BPAD 72

// ---------------------------------------------------------------------------
// Device scratch (static, allocation-free)
// ---------------------------------------------------------------------------
__device__ float g_xnorm[(size_t)NTOK * DD];              // 8 MB
__device__ float g_hidden[(size_t)NROWS * HH];            // 32 MB
__device__ float g_y[(size_t)NROWS * DD];                 // 16 MB
__device__ int   g_counts[EE];
__device__ int   g_rowid[EE * NROWS];
__device__ float g_assign_w[NROWS];

__global__ void zero_counts_kernel() {
    if (threadIdx.x < EE) g_counts[threadIdx.x] = 0;
}

__device__ __forceinline__ float silu_f(float v) {
    return v / (1.0f + expf(-v));
}

// mma.sync m16n8k16 bf16 + split helpers (proven R8/R9)
__device__ __forceinline__ void mma16816(float* c, const uint32_t* a, const uint32_t* b) {
    asm volatile("mma.sync.aligned.m16n8k16.row.col.f32.bf16.bf16.f32 "
                 "{%0,%1,%2,%3}, {%4,%5,%6,%7}, {%8,%9}, {%0,%1,%2,%3};"
                 : "+f"(c[0]), "+f"(c[1]), "+f"(c[2]), "+f"(c[3])
                 : "r"(a[0]), "r"(a[1]), "r"(a[2]), "r"(a[3]), "r"(b[0]), "r"(b[1]));
}
__device__ __forceinline__ void splitpack(float f0, float f1, uint32_t& hi, uint32_t& lo) {
    __nv_bfloat162 h, l;
    h.x = __float2bfloat16(f0);
    h.y = __float2bfloat16(f1);
    l.x = __float2bfloat16(f0 - __bfloat162float(h.x));
    l.y = __float2bfloat16(f1 - __bfloat162float(h.y));
    hi = *(uint32_t*)&h;
    lo = *(uint32_t*)&l;
}

// ---------------------------------------------------------------------------
// Kernel A: RMSNorm + router (proven)
// ---------------------------------------------------------------------------
__global__ void __launch_bounds__(256) norm_router_kernel(
    const float* __restrict__ x, const float* __restrict__ gvec,
    const float* __restrict__ gate_w)
{
    const int t   = blockIdx.x;
    const int tid = threadIdx.x;
    __shared__ float sh[DD];
    __shared__ float red[8];
    __shared__ float logit[EE];

    const float4 v = ((const float4*)(x + (size_t)t * DD))[tid];
    float ss = v.x*v.x + v.y*v.y + v.z*v.z + v.w*v.w;
    #pragma unroll
    for (int o = 16; o; o >>= 1) ss += __shfl_xor_sync(0xffffffffu, ss, o);
    if ((tid & 31) == 0) red[tid >> 5] = ss;
    __syncthreads();
    if (tid < 8) {
        float s = red[tid];
        #pragma unroll
        for (int o = 4; o; o >>= 1) s += __shfl_xor_sync(0xffu, s, o);
        if (tid == 0) red[0] = s;
    }
    __syncthreads();
    const float rinv = rsqrtf(red[0] * (1.0f / DD) + 1e-5f);
    const float4 gv = ((const float4*)gvec)[tid];
    float4 xn;
    xn.x = v.x * rinv * gv.x;
    xn.y = v.y * rinv * gv.y;
    xn.z = v.z * rinv * gv.z;
    xn.w = v.w * rinv * gv.w;
    ((float4*)sh)[tid] = xn;
    ((float4*)(g_xnorm + (size_t)t * DD))[tid] = xn;
    __syncthreads();

    const int w = tid >> 5, lane = tid & 31;
    float acc = 0.f;
    const float* gw = gate_w + (size_t)w * DD;
    for (int d = lane; d < DD; d += 32) acc += sh[d] * gw[d];
    #pragma unroll
    for (int o = 16; o; o >>= 1) acc += __shfl_xor_sync(0xffffffffu, acc, o);
    if (lane == 0) logit[w] = acc;
    __syncthreads();

    if (tid == 0) {
        float mx = logit[0];
        #pragma unroll
        for (int e = 1; e < EE; e++) mx = fmaxf(mx, logit[e]);
        float p[EE]; float Z = 0.f;
        #pragma unroll
        for (int e = 0; e < EE; e++) { p[e] = expf(logit[e] - mx); Z += p[e]; }
        const float iz = 1.f / Z;
        #pragma unroll
        for (int e = 0; e < EE; e++) p[e] *= iz;
        int i0 = 0;
        #pragma unroll
        for (int e = 1; e < EE; e++) if (p[e] > p[i0]) i0 = e;
        int i1 = (i0 == 0) ? 1 : 0;
        #pragma unroll
        for (int e = 0; e < EE; e++) if (e != i1 && e != i0 && p[e] > p[i1]) i1 = e;
        const float denom = p[i0] + p[i1] + 1e-10f;
        int pos0 = atomicAdd(&g_counts[i0], 1);
        g_rowid[i0 * NROWS + pos0] = t * 2 + 0;
        g_assign_w[t * 2 + 0] = p[i0] / denom;
        int pos1 = atomicAdd(&g_counts[i1], 1);
        g_rowid[i1 * NROWS + pos1] = t * 2 + 1;
        g_assign_w[t * 2 + 1] = p[i1] / denom;
    }
}

// ---------------------------------------------------------------------------
// GEMM1 (mma, 3-term split, in-kernel): hidden = silu(Xg@w1) * (Xg@w2)
// CTA 128M x 64N dual-B, 8 warps (4m x 2n). Conflict-free padded smem.
// ---------------------------------------------------------------------------
__global__ void __launch_bounds__(256) mma_gemm1_kernel(
    const float* __restrict__ w1, const float* __restrict__ w2)
{
    const int e = blockIdx.z, mtb = blockIdx.y, ntb = blockIdx.x;
    const int ne = g_counts[e];
    if (mtb * 128 >= ne) return;

    __shared__ uint32_t AHi[2][8][APAD], ALo[2][8][APAD];
    __shared__ uint32_t B1Hi[2][8][BPAD], B1Lo[2][8][BPAD];
    __shared__ uint32_t B2Hi[2][8][BPAD], B2Lo[2][8][BPAD];
    __shared__ int rows[128];

    const int tid = threadIdx.x;
    if (tid < 128) {
        const int m = mtb * 128 + tid;
        rows[tid] = (m < ne) ? g_rowid[e * NROWS + m] : -1;
    }
    __syncthreads();

    // A loader: one row per thread (mod 128), k-half from tid>>7 (bank-friendly STS)
    const int arow = tid & 127, ahalf = tid >> 7;
    const int rA = rows[arow];
    const float* aptr = (rA >= 0) ? (g_xnorm + (size_t)(rA >> 1) * DD) : g_xnorm;
    // B loader: threads 0-127 -> w1, 128-255 -> w2. Within half: kp=0..7, nq=0..15
    const int bhalf = tid >> 7;
    const int bkp = (tid & 127) >> 4, bnq = tid & 15;
    const float* bp = (bhalf == 0 ? w1 : w2) + (size_t)e * DD * HH + ntb * 64;

    float4 fa0, fa1, fb0, fb1;
    auto ldg = [&](int i) {
        const int k0 = i * 16;
        if (rA >= 0) {
            fa0 = *(const float4*)(aptr + k0 + ahalf * 8);
            fa1 = *(const float4*)(aptr + k0 + ahalf * 8 + 4);
        } else {
            fa0 = make_float4(0.f, 0.f, 0.f, 0.f);
            fa1 = fa0;
        }
        fb0 = *(const float4*)(bp + (size_t)(k0 + 2 * bkp)     * HH + bnq * 4);
        fb1 = *(const float4*)(bp + (size_t)(k0 + 2 * bkp + 1) * HH + bnq * 4);
    };
    auto sts = [&](int buf) {
        uint32_t hi, lo;
        const float fa[8] = {fa0.x, fa0.y, fa0.z, fa0.w, fa1.x, fa1.y, fa1.z, fa1.w};
        #pragma unroll
        for (int j = 0; j < 4; j++) {
            splitpack(fa[2*j], fa[2*j+1], hi, lo);
            AHi[buf][ahalf * 4 + j][arow] = hi;
            ALo[buf][ahalf * 4 + j][arow] = lo;
        }
        uint32_t h4[4], l4v[4];
        splitpack(fb0.x, fb1.x, h4[0], l4v[0]);
        splitpack(fb0.y, fb1.y, h4[1], l4v[1]);
        splitpack(fb0.z, fb1.z, h4[2], l4v[2]);
        splitpack(fb0.w, fb1.w, h4[3], l4v[3]);
        if (bhalf == 0) {
            *(uint4*)&B1Hi[buf][bkp][bnq * 4] = make_uint4(h4[0], h4[1], h4[2], h4[3]);
            *(uint4*)&B1Lo[buf][bkp][bnq * 4] = make_uint4(l4v[0], l4v[1], l4v[2], l4v[3]);
        } else {
            *(uint4*)&B2Hi[buf][bkp][bnq * 4] = make_uint4(h4[0], h4[1], h4[2], h4[3]);
            *(uint4*)&B2Lo[buf][bkp][bnq * 4] = make_uint4(l4v[0], l4v[1], l4v[2], l4v[3]);
        }
    };
    ldg(0); sts(0); __syncthreads();

    const int lane = tid & 31, wid = tid >> 5;
    const int wm = wid & 3, wn = wid >> 2;
    const int l4 = lane >> 2, lp = lane & 3;

    float acc1[2][4][4] = {};
    float acc2[2][4][4] = {};

    for (int i = 0; i < 64; i++) {
        if (i + 1 < 64) ldg(i + 1);
        const int buf = i & 1;
        uint32_t aHi[2][4], aLo[2][4];
        uint32_t b1h[4][2], b1l[4][2], b2h[4][2], b2l[4][2];
        #pragma unroll
        for (int mt = 0; mt < 2; mt++) {
            const int M0 = wm * 32 + mt * 16 + l4;
            aHi[mt][0] = AHi[buf][lp][M0];       aHi[mt][1] = AHi[buf][lp][M0 + 8];
            aHi[mt][2] = AHi[buf][lp + 4][M0];   aHi[mt][3] = AHi[buf][lp + 4][M0 + 8];
            aLo[mt][0] = ALo[buf][lp][M0];       aLo[mt][1] = ALo[buf][lp][M0 + 8];
            aLo[mt][2] = ALo[buf][lp + 4][M0];   aLo[mt][3] = ALo[buf][lp + 4][M0 + 8];
        }
        #pragma unroll
        for (int nt = 0; nt < 4; nt++) {
            const int N0 = wn * 32 + nt * 8 + l4;
            b1h[nt][0] = B1Hi[buf][lp][N0];      b1h[nt][1] = B1Hi[buf][lp + 4][N0];
            b1l[nt][0] = B1Lo[buf][lp][N0];      b1l[nt][1] = B1Lo[buf][lp + 4][N0];
            b2h[nt][0] = B2Hi[buf][lp][N0];      b2h[nt][1] = B2Hi[buf][lp + 4][N0];
            b2l[nt][0] = B2Lo[buf][lp][N0];      b2l[nt][1] = B2Lo[buf][lp + 4][N0];
        }
        #pragma unroll
        for (int mt = 0; mt < 2; mt++) {
            #pragma unroll
            for (int nt = 0; nt < 4; nt++) {
                mma16816(acc1[mt][nt], aHi[mt], b1h[nt]);
                mma16816(acc1[mt][nt], aLo[mt], b1h[nt]);
                mma16816(acc1[mt][nt], aHi[mt], b1l[nt]);
                mma16816(acc2[mt][nt], aHi[mt], b2h[nt]);
                mma16816(acc2[mt][nt], aLo[mt], b2h[nt]);
                mma16816(acc2[mt][nt], aHi[mt], b2l[nt]);
            }
        }
        if (i + 1 < 64) sts((i + 1) & 1);
        __syncthreads();
    }

    const int hbase = ntb * 64;
    const int mrow0 = wm * 32 + l4;
    const int ncol0 = wn * 32 + 2 * lp;
    #pragma unroll
    for (int mt = 0; mt < 2; mt++) {
        #pragma unroll
        for (int h = 0; h < 2; h++) {
            const int ml = mrow0 + mt * 16 + h * 8;
            const int r = rows[ml];
            if (r < 0) continue;
            float* hrow = g_hidden + (size_t)r * HH + hbase;
            #pragma unroll
            for (int nt = 0; nt < 4; nt++) {
                const float g1a = acc1[mt][nt][2*h], g1b = acc1[mt][nt][2*h+1];
                const float g2a = acc2[mt][nt][2*h], g2b = acc2[mt][nt][2*h+1];
                float2 o;
                o.x = silu_f(g1a) * g2a;
                o.y = silu_f(g1b) * g2b;
                *(float2*)(hrow + ncol0 + nt * 8) = o;
            }
        }
    }
}

// ---------------------------------------------------------------------------
// GEMM2 (mma, 3-term split, in-kernel): y = hidden @ w3[e]. CTA 128M x 64N.
// ---------------------------------------------------------------------------
__global__ void __launch_bounds__(256) mma_gemm2_kernel(const float* __restrict__ w3)
{
    const int e = blockIdx.z, mtb = blockIdx.y, ntb = blockIdx.x;
    const int ne = g_counts[e];
    if (mtb * 128 >= ne) return;

    __shared__ uint32_t AHi[2][8][APAD], ALo[2][8][APAD];
    __shared__ uint32_t BHi[2][8][BPAD], BLo[2][8][BPAD];
    __shared__ int rows[128];

    const int tid = threadIdx.x;
    if (tid < 128) {
        const int m = mtb * 128 + tid;
        rows[tid] = (m < ne) ? g_rowid[e * NROWS + m] : -1;
    }
    __syncthreads();

    const int arow = tid & 127, ahalf = tid >> 7;
    const int rA = rows[arow];
    const float* aptr = (rA >= 0) ? (g_hidden + (size_t)rA * HH) : g_hidden;
    const int bkp = tid >> 4, bnq = tid & 15;
    const float* bp = w3 + (size_t)e * HH * DD + ntb * 64;

    float4 fa0, fa1, fb0, fb1;
    auto ldg = [&](int i) {
        const int k0 = i * 16;
        if (rA >= 0) {
            fa0 = *(const float4*)(aptr + k0 + ahalf * 8);
            fa1 = *(const float4*)(aptr + k0 + ahalf * 8 + 4);
        } else {
            fa0 = make_float4(0.f, 0.f, 0.f, 0.f);
            fa1 = fa0;
        }
        if (tid < 128) {
            fb0 = *(const float4*)(bp + (size_t)(k0 + 2 * bkp)     * DD + bnq * 4);
            fb1 = *(const float4*)(bp + (size_t)(k0 + 2 * bkp + 1) * DD + bnq * 4);
        }
    };
    auto sts = [&](int buf) {
        uint32_t hi, lo;
        const float fa[8] = {fa0.x, fa0.y, fa0.z, fa0.w, fa1.x, fa1.y, fa1.z, fa1.w};
        #pragma unroll
        for (int j = 0; j < 4; j++) {
            splitpack(fa[2*j], fa[2*j+1], hi, lo);
            AHi[buf][ahalf * 4 + j][arow] = hi;
            ALo[buf][ahalf * 4 + j][arow] = lo;
        }
        if (tid < 128) {
            uint32_t h4[4], l4v[4];
            splitpack(fb0.x, fb1.x, h4[0], l4v[0]);
            splitpack(fb0.y, fb1.y, h4[1], l4v[1]);
            splitpack(fb0.z, fb1.z, h4[2], l4v[2]);
            splitpack(fb0.w, fb1.w, h4[3], l4v[3]);
            *(uint4*)&BHi[buf][bkp][bnq * 4] = make_uint4(h4[0], h4[1], h4[2], h4[3]);
            *(uint4*)&BLo[buf][bkp][bnq * 4] = make_uint4(l4v[0], l4v[1], l4v[2], l4v[3]);
        }
    };
    ldg(0); sts(0); __syncthreads();

    const int lane = tid & 31, wid = tid >> 5;
    const int wm = wid & 3, wn = wid >> 2;
    const int l4 = lane >> 2, lp = lane & 3;

    float acc[2][4][4] = {};

    for (int i = 0; i < 128; i++) {
        if (i + 1 < 128) ldg(i + 1);
        const int buf = i & 1;
        uint32_t aHi[2][4], aLo[2][4], bHi[4][2], bLo[4][2];
        #pragma unroll
        for (int mt = 0; mt < 2; mt++) {
            const int M0 = wm * 32 + mt * 16 + l4;
            aHi[mt][0] = AHi[buf][lp][M0];       aHi[mt][1] = AHi[buf][lp][M0 + 8];
            aHi[mt][2] = AHi[buf][lp + 4][M0];   aHi[mt][3] = AHi[buf][lp + 4][M0 + 8];
            aLo[mt][0] = ALo[buf][lp][M0];       aLo[mt][1] = ALo[buf][lp][M0 + 8];
            aLo[mt][2] = ALo[buf][lp + 4][M0];   aLo[mt][3] = ALo[buf][lp + 4][M0 + 8];
        }
        #pragma unroll
        for (int nt = 0; nt < 4; nt++) {
            const int N0 = wn * 32 + nt * 8 + l4;
            bHi[nt][0] = BHi[buf][lp][N0];       bHi[nt][1] = BHi[buf][lp + 4][N0];
            bLo[nt][0] = BLo[buf][lp][N0];       bLo[nt][1] = BLo[buf][lp + 4][N0];
        }
        #pragma unroll
        for (int mt = 0; mt < 2; mt++) {
            #pragma unroll
            for (int nt = 0; nt < 4; nt++) {
                mma16816(acc[mt][nt], aHi[mt], bHi[nt]);
                mma16816(acc[mt][nt], aLo[mt], bHi[nt]);
                mma16816(acc[mt][nt], aHi[mt], bLo[nt]);
            }
        }
        if (i + 1 < 128) sts((i + 1) & 1);
        __syncthreads();
    }

    const int dbase = ntb * 64;
    const int mrow0 = wm * 32 + l4;
    const int ncol0 = wn * 32 + 2 * lp;
    #pragma unroll
    for (int mt = 0; mt < 2; mt++) {
        #pragma unroll
        for (int h = 0; h < 2; h++) {
            const int ml = mrow0 + mt * 16 + h * 8;
            const int r = rows[ml];
            if (r < 0) continue;
            float* yrow = g_y + (size_t)r * DD + dbase;
            #pragma unroll
            for (int nt = 0; nt < 4; nt++) {
                float2 o;
                o.x = acc[mt][nt][2*h];
                o.y = acc[mt][nt][2*h+1];
                *(float2*)(yrow + ncol0 + nt * 8) = o;
            }
        }
    }
}

// ---------------------------------------------------------------------------
// Kernel D: combine out[t] = w0*y[2t] + w1*y[2t+1]
// ---------------------------------------------------------------------------
__global__ void __launch_bounds__(256) combine_kernel(float* __restrict__ out)
{
    const int t   = blockIdx.x;
    const int tid = threadIdx.x;
    const float w0 = g_assign_w[2 * t + 0];
    const float w1 = g_assign_w[2 * t + 1];
    const float4 a = ((const float4*)(g_y + (size_t)(2 * t + 0) * DD))[tid];
    const float4 b = ((const float4*)(g_y + (size_t)(2 * t + 1) * DD))[tid];
    float4 o;
    o.x = w0 * a.x + w1 * b.x;
    o.y = w0 * a.y + w1 * b.y;
    o.z = w0 * a.z + w1 * b.z;
    o.w = w0 * a.w + w1 * b.w;
    ((float4*)(out + (size_t)t * DD))[tid] = o;
}

// ---------------------------------------------------------------------------
extern "C" void kernel_launch(void* const* d_in, const int* in_sizes, int n_in,
                              void* d_out, int out_size)
{
    const float* x      = (const float*)d_in[0];
    const float* gvec   = (const float*)d_in[1];
    const float* gate_w = (const float*)d_in[2];
    const float* w1     = (const float*)d_in[3];
    const float* w2     = (const float*)d_in[4];
    const float* w3     = (const float*)d_in[5];
    float* out = (float*)d_out;

    zero_counts_kernel<<<1, 32>>>();
    norm_router_kernel<<<NTOK, 256>>>(x, gvec, gate_w);
    mma_gemm1_kernel<<<dim3(HH / 64, NROWS / 128, EE), 256>>>(w1, w2);
    mma_gemm2_kernel<<<dim3(DD / 64, NROWS / 128, EE), 256>>>(w3);
    combine_kernel<<<NTOK, 256>>>(out);
}

// round 15
// speedup vs baseline: 1.0043x; 1.0043x over previous
#include <cuda_runtime.h>
#include <cuda_bf16.h>
#include <math.h>
#include <stdint.h>

// Problem constants
#define NTOK   2048
#define DD     1024
#define HH     2048
#define EE     8
#define NROWS  4096        // NTOK * topk(2) slot-rows

// ---------------------------------------------------------------------------
// Device scratch (static, allocation-free)
// ---------------------------------------------------------------------------
__device__ float g_xnorm[(size_t)NTOK * DD];              // 8 MB
__device__ float g_hidden[(size_t)NROWS * HH];            // 32 MB
__device__ float g_y[(size_t)NROWS * DD];                 // 16 MB
__device__ int   g_counts[EE];
__device__ int   g_rowid[EE * NROWS];
__device__ float g_assign_w[NROWS];

__global__ void zero_counts_kernel() {
    if (threadIdx.x < EE) g_counts[threadIdx.x] = 0;
}

__device__ __forceinline__ float silu_f(float v) {
    return v / (1.0f + expf(-v));
}

// mma.sync m16n8k16 bf16 + split helpers (proven R8/R9)
__device__ __forceinline__ void mma16816(float* c, const uint32_t* a, const uint32_t* b) {
    asm volatile("mma.sync.aligned.m16n8k16.row.col.f32.bf16.bf16.f32 "
                 "{%0,%1,%2,%3}, {%4,%5,%6,%7}, {%8,%9}, {%0,%1,%2,%3};"
                 : "+f"(c[0]), "+f"(c[1]), "+f"(c[2]), "+f"(c[3])
                 : "r"(a[0]), "r"(a[1]), "r"(a[2]), "r"(a[3]), "r"(b[0]), "r"(b[1]));
}
__device__ __forceinline__ void splitpack(float f0, float f1, uint32_t& hi, uint32_t& lo) {
    __nv_bfloat162 h, l;
    h.x = __float2bfloat16(f0);
    h.y = __float2bfloat16(f1);
    l.x = __float2bfloat16(f0 - __bfloat162float(h.x));
    l.y = __float2bfloat16(f1 - __bfloat162float(h.y));
    hi = *(uint32_t*)&h;
    lo = *(uint32_t*)&l;
}

// ---------------------------------------------------------------------------
// Kernel A: RMSNorm + router (proven)
// ---------------------------------------------------------------------------
__global__ void __launch_bounds__(256) norm_router_kernel(
    const float* __restrict__ x, const float* __restrict__ gvec,
    const float* __restrict__ gate_w)
{
    const int t   = blockIdx.x;
    const int tid = threadIdx.x;
    __shared__ float sh[DD];
    __shared__ float red[8];
    __shared__ float logit[EE];

    const float4 v = ((const float4*)(x + (size_t)t * DD))[tid];
    float ss = v.x*v.x + v.y*v.y + v.z*v.z + v.w*v.w;
    #pragma unroll
    for (int o = 16; o; o >>= 1) ss += __shfl_xor_sync(0xffffffffu, ss, o);
    if ((tid & 31) == 0) red[tid >> 5] = ss;
    __syncthreads();
    if (tid < 8) {
        float s = red[tid];
        #pragma unroll
        for (int o = 4; o; o >>= 1) s += __shfl_xor_sync(0xffu, s, o);
        if (tid == 0) red[0] = s;
    }
    __syncthreads();
    const float rinv = rsqrtf(red[0] * (1.0f / DD) + 1e-5f);
    const float4 gv = ((const float4*)gvec)[tid];
    float4 xn;
    xn.x = v.x * rinv * gv.x;
    xn.y = v.y * rinv * gv.y;
    xn.z = v.z * rinv * gv.z;
    xn.w = v.w * rinv * gv.w;
    ((float4*)sh)[tid] = xn;
    ((float4*)(g_xnorm + (size_t)t * DD))[tid] = xn;
    __syncthreads();

    const int w = tid >> 5, lane = tid & 31;
    float acc = 0.f;
    const float* gw = gate_w + (size_t)w * DD;
    for (int d = lane; d < DD; d += 32) acc += sh[d] * gw[d];
    #pragma unroll
    for (int o = 16; o; o >>= 1) acc += __shfl_xor_sync(0xffffffffu, acc, o);
    if (lane == 0) logit[w] = acc;
    __syncthreads();

    if (tid == 0) {
        float mx = logit[0];
        #pragma unroll
        for (int e = 1; e < EE; e++) mx = fmaxf(mx, logit[e]);
        float p[EE]; float Z = 0.f;
        #pragma unroll
        for (int e = 0; e < EE; e++) { p[e] = expf(logit[e] - mx); Z += p[e]; }
        const float iz = 1.f / Z;
        #pragma unroll
        for (int e = 0; e < EE; e++) p[e] *= iz;
        int i0 = 0;
        #pragma unroll
        for (int e = 1; e < EE; e++) if (p[e] > p[i0]) i0 = e;
        int i1 = (i0 == 0) ? 1 : 0;
        #pragma unroll
        for (int e = 0; e < EE; e++) if (e != i1 && e != i0 && p[e] > p[i1]) i1 = e;
        const float denom = p[i0] + p[i1] + 1e-10f;
        int pos0 = atomicAdd(&g_counts[i0], 1);
        g_rowid[i0 * NROWS + pos0] = t * 2 + 0;
        g_assign_w[t * 2 + 0] = p[i0] / denom;
        int pos1 = atomicAdd(&g_counts[i1], 1);
        g_rowid[i1 * NROWS + pos1] = t * 2 + 1;
        g_assign_w[t * 2 + 1] = p[i1] / denom;
    }
}

// ---------------------------------------------------------------------------
// GEMM1 (mma, 3-term split, in-kernel): hidden = silu(Xg@w1) * (Xg@w2)
// CTA 128M x 64N dual-B, 8 warps (4m x 2n). R9 layout; reg cap for 2 CTAs/SM.
// ---------------------------------------------------------------------------
__global__ void __launch_bounds__(256, 2) mma_gemm1_kernel(
    const float* __restrict__ w1, const float* __restrict__ w2)
{
    const int e = blockIdx.z, mtb = blockIdx.y, ntb = blockIdx.x;
    const int ne = g_counts[e];
    if (mtb * 128 >= ne) return;

    __shared__ uint32_t AHi[2][8][132], ALo[2][8][132];
    __shared__ uint32_t B1Hi[2][8][68], B1Lo[2][8][68];
    __shared__ uint32_t B2Hi[2][8][68], B2Lo[2][8][68];
    __shared__ int rows[128];

    const int tid = threadIdx.x;
    if (tid < 128) {
        const int m = mtb * 128 + tid;
        rows[tid] = (m < ne) ? g_rowid[e * NROWS + m] : -1;
    }
    __syncthreads();

    // A loader: 2 threads/row, each 8 k's
    const int arow = tid >> 1, ahalf = tid & 1;
    const int rA = rows[arow];
    const float* aptr = (rA >= 0) ? (g_xnorm + (size_t)(rA >> 1) * DD) : g_xnorm;
    // B loader: threads 0-127 -> w1, 128-255 -> w2. Within half: kp=0..7, nq=0..15
    const int bhalf = tid >> 7;
    const int bkp = (tid & 127) >> 4, bnq = tid & 15;
    const float* bp = (bhalf == 0 ? w1 : w2) + (size_t)e * DD * HH + ntb * 64;

    float4 fa0, fa1, fb0, fb1;
    auto ldg = [&](int i) {
        const int k0 = i * 16;
        if (rA >= 0) {
            fa0 = *(const float4*)(aptr + k0 + ahalf * 8);
            fa1 = *(const float4*)(aptr + k0 + ahalf * 8 + 4);
        } else {
            fa0 = make_float4(0.f, 0.f, 0.f, 0.f);
            fa1 = fa0;
        }
        fb0 = *(const float4*)(bp + (size_t)(k0 + 2 * bkp)     * HH + bnq * 4);
        fb1 = *(const float4*)(bp + (size_t)(k0 + 2 * bkp + 1) * HH + bnq * 4);
    };
    auto sts = [&](int buf) {
        uint32_t hi, lo;
        const float fa[8] = {fa0.x, fa0.y, fa0.z, fa0.w, fa1.x, fa1.y, fa1.z, fa1.w};
        #pragma unroll
        for (int j = 0; j < 4; j++) {
            splitpack(fa[2*j], fa[2*j+1], hi, lo);
            AHi[buf][ahalf * 4 + j][arow] = hi;
            ALo[buf][ahalf * 4 + j][arow] = lo;
        }
        uint32_t h4[4], l4v[4];
        splitpack(fb0.x, fb1.x, h4[0], l4v[0]);
        splitpack(fb0.y, fb1.y, h4[1], l4v[1]);
        splitpack(fb0.z, fb1.z, h4[2], l4v[2]);
        splitpack(fb0.w, fb1.w, h4[3], l4v[3]);
        if (bhalf == 0) {
            *(uint4*)&B1Hi[buf][bkp][bnq * 4] = make_uint4(h4[0], h4[1], h4[2], h4[3]);
            *(uint4*)&B1Lo[buf][bkp][bnq * 4] = make_uint4(l4v[0], l4v[1], l4v[2], l4v[3]);
        } else {
            *(uint4*)&B2Hi[buf][bkp][bnq * 4] = make_uint4(h4[0], h4[1], h4[2], h4[3]);
            *(uint4*)&B2Lo[buf][bkp][bnq * 4] = make_uint4(l4v[0], l4v[1], l4v[2], l4v[3]);
        }
    };
    ldg(0); sts(0); __syncthreads();

    const int lane = tid & 31, wid = tid >> 5;
    const int wm = wid & 3, wn = wid >> 2;
    const int l4 = lane >> 2, lp = lane & 3;

    float acc1[2][4][4] = {};
    float acc2[2][4][4] = {};

    for (int i = 0; i < 64; i++) {
        if (i + 1 < 64) ldg(i + 1);
        const int buf = i & 1;
        uint32_t aHi[2][4], aLo[2][4];
        uint32_t b1h[4][2], b1l[4][2], b2h[4][2], b2l[4][2];
        #pragma unroll
        for (int mt = 0; mt < 2; mt++) {
            const int M0 = wm * 32 + mt * 16 + l4;
            aHi[mt][0] = AHi[buf][lp][M0];       aHi[mt][1] = AHi[buf][lp][M0 + 8];
            aHi[mt][2] = AHi[buf][lp + 4][M0];   aHi[mt][3] = AHi[buf][lp + 4][M0 + 8];
            aLo[mt][0] = ALo[buf][lp][M0];       aLo[mt][1] = ALo[buf][lp][M0 + 8];
            aLo[mt][2] = ALo[buf][lp + 4][M0];   aLo[mt][3] = ALo[buf][lp + 4][M0 + 8];
        }
        #pragma unroll
        for (int nt = 0; nt < 4; nt++) {
            const int N0 = wn * 32 + nt * 8 + l4;
            b1h[nt][0] = B1Hi[buf][lp][N0];      b1h[nt][1] = B1Hi[buf][lp + 4][N0];
            b1l[nt][0] = B1Lo[buf][lp][N0];      b1l[nt][1] = B1Lo[buf][lp + 4][N0];
            b2h[nt][0] = B2Hi[buf][lp][N0];      b2h[nt][1] = B2Hi[buf][lp + 4][N0];
            b2l[nt][0] = B2Lo[buf][lp][N0];      b2l[nt][1] = B2Lo[buf][lp + 4][N0];
        }
        #pragma unroll
        for (int mt = 0; mt < 2; mt++) {
            #pragma unroll
            for (int nt = 0; nt < 4; nt++) {
                mma16816(acc1[mt][nt], aHi[mt], b1h[nt]);
                mma16816(acc1[mt][nt], aLo[mt], b1h[nt]);
                mma16816(acc1[mt][nt], aHi[mt], b1l[nt]);
                mma16816(acc2[mt][nt], aHi[mt], b2h[nt]);
                mma16816(acc2[mt][nt], aLo[mt], b2h[nt]);
                mma16816(acc2[mt][nt], aHi[mt], b2l[nt]);
            }
        }
        if (i + 1 < 64) sts((i + 1) & 1);
        __syncthreads();
    }

    const int hbase = ntb * 64;
    const int mrow0 = wm * 32 + l4;
    const int ncol0 = wn * 32 + 2 * lp;
    #pragma unroll
    for (int mt = 0; mt < 2; mt++) {
        #pragma unroll
        for (int h = 0; h < 2; h++) {
            const int ml = mrow0 + mt * 16 + h * 8;
            const int r = rows[ml];
            if (r < 0) continue;
            float* hrow = g_hidden + (size_t)r * HH + hbase;
            #pragma unroll
            for (int nt = 0; nt < 4; nt++) {
                const float g1a = acc1[mt][nt][2*h], g1b = acc1[mt][nt][2*h+1];
                const float g2a = acc2[mt][nt][2*h], g2b = acc2[mt][nt][2*h+1];
                float2 o;
                o.x = silu_f(g1a) * g2a;
                o.y = silu_f(g1b) * g2b;
                *(float2*)(hrow + ncol0 + nt * 8) = o;
            }
        }
    }
}

// ---------------------------------------------------------------------------
// GEMM2 (mma, 3-term split, in-kernel): y = hidden @ w3[e]. CTA 128M x 64N.
// R9 layout; reg cap for 3 CTAs/SM (occupancy 24% -> 36%).
// ---------------------------------------------------------------------------
__global__ void __launch_bounds__(256, 3) mma_gemm2_kernel(const float* __restrict__ w3)
{
    const int e = blockIdx.z, mtb = blockIdx.y, ntb = blockIdx.x;
    const int ne = g_counts[e];
    if (mtb * 128 >= ne) return;

    __shared__ uint32_t AHi[2][8][132], ALo[2][8][132];
    __shared__ uint32_t BHi[2][8][68],  BLo[2][8][68];
    __shared__ int rows[128];

    const int tid = threadIdx.x;
    if (tid < 128) {
        const int m = mtb * 128 + tid;
        rows[tid] = (m < ne) ? g_rowid[e * NROWS + m] : -1;
    }
    __syncthreads();

    const int arow = tid >> 1, ahalf = tid & 1;
    const int rA = rows[arow];
    const float* aptr = (rA >= 0) ? (g_hidden + (size_t)rA * HH) : g_hidden;
    const int bkp = tid >> 4, bnq = tid & 15;
    const float* bp = w3 + (size_t)e * HH * DD + ntb * 64;

    float4 fa0, fa1, fb0, fb1;
    auto ldg = [&](int i) {
        const int k0 = i * 16;
        if (rA >= 0) {
            fa0 = *(const float4*)(aptr + k0 + ahalf * 8);
            fa1 = *(const float4*)(aptr + k0 + ahalf * 8 + 4);
        } else {
            fa0 = make_float4(0.f, 0.f, 0.f, 0.f);
            fa1 = fa0;
        }
        if (tid < 128) {
            fb0 = *(const float4*)(bp + (size_t)(k0 + 2 * bkp)     * DD + bnq * 4);
            fb1 = *(const float4*)(bp + (size_t)(k0 + 2 * bkp + 1) * DD + bnq * 4);
        }
    };
    auto sts = [&](int buf) {
        uint32_t hi, lo;
        const float fa[8] = {fa0.x, fa0.y, fa0.z, fa0.w, fa1.x, fa1.y, fa1.z, fa1.w};
        #pragma unroll
        for (int j = 0; j < 4; j++) {
            splitpack(fa[2*j], fa[2*j+1], hi, lo);
            AHi[buf][ahalf * 4 + j][arow] = hi;
            ALo[buf][ahalf * 4 + j][arow] = lo;
        }
        if (tid < 128) {
            uint32_t h4[4], l4v[4];
            splitpack(fb0.x, fb1.x, h4[0], l4v[0]);
            splitpack(fb0.y, fb1.y, h4[1], l4v[1]);
            splitpack(fb0.z, fb1.z, h4[2], l4v[2]);
            splitpack(fb0.w, fb1.w, h4[3], l4v[3]);
            *(uint4*)&BHi[buf][bkp][bnq * 4] = make_uint4(h4[0], h4[1], h4[2], h4[3]);
            *(uint4*)&BLo[buf][bkp][bnq * 4] = make_uint4(l4v[0], l4v[1], l4v[2], l4v[3]);
        }
    };
    ldg(0); sts(0); __syncthreads();

    const int lane = tid & 31, wid = tid >> 5;
    const int wm = wid & 3, wn = wid >> 2;
    const int l4 = lane >> 2, lp = lane & 3;

    float acc[2][4][4] = {};

    for (int i = 0; i < 128; i++) {
        if (i + 1 < 128) ldg(i + 1);
        const int buf = i & 1;
        uint32_t aHi[2][4], aLo[2][4], bHi[4][2], bLo[4][2];
        #pragma unroll
        for (int mt = 0; mt < 2; mt++) {
            const int M0 = wm * 32 + mt * 16 + l4;
            aHi[mt][0] = AHi[buf][lp][M0];       aHi[mt][1] = AHi[buf][lp][M0 + 8];
            aHi[mt][2] = AHi[buf][lp + 4][M0];   aHi[mt][3] = AHi[buf][lp + 4][M0 + 8];
            aLo[mt][0] = ALo[buf][lp][M0];       aLo[mt][1] = ALo[buf][lp][M0 + 8];
            aLo[mt][2] = ALo[buf][lp + 4][M0];   aLo[mt][3] = ALo[buf][lp + 4][M0 + 8];
        }
        #pragma unroll
        for (int nt = 0; nt < 4; nt++) {
            const int N0 = wn * 32 + nt * 8 + l4;
            bHi[nt][0] = BHi[buf][lp][N0];       bHi[nt][1] = BHi[buf][lp + 4][N0];
            bLo[nt][0] = BLo[buf][lp][N0];       bLo[nt][1] = BLo[buf][lp + 4][N0];
        }
        #pragma unroll
        for (int mt = 0; mt < 2; mt++) {
            #pragma unroll
            for (int nt = 0; nt < 4; nt++) {
                mma16816(acc[mt][nt], aHi[mt], bHi[nt]);
                mma16816(acc[mt][nt], aLo[mt], bHi[nt]);
                mma16816(acc[mt][nt], aHi[mt], bLo[nt]);
            }
        }
        if (i + 1 < 128) sts((i + 1) & 1);
        __syncthreads();
    }

    const int dbase = ntb * 64;
    const int mrow0 = wm * 32 + l4;
    const int ncol0 = wn * 32 + 2 * lp;
    #pragma unroll
    for (int mt = 0; mt < 2; mt++) {
        #pragma unroll
        for (int h = 0; h < 2; h++) {
            const int ml = mrow0 + mt * 16 + h * 8;
            const int r = rows[ml];
            if (r < 0) continue;
            float* yrow = g_y + (size_t)r * DD + dbase;
            #pragma unroll
            for (int nt = 0; nt < 4; nt++) {
                float2 o;
                o.x = acc[mt][nt][2*h];
                o.y = acc[mt][nt][2*h+1];
                *(float2*)(yrow + ncol0 + nt * 8) = o;
            }
        }
    }
}

// ---------------------------------------------------------------------------
// Kernel D: combine out[t] = w0*y[2t] + w1*y[2t+1]
// ---------------------------------------------------------------------------
__global__ void __launch_bounds__(256) combine_kernel(float* __restrict__ out)
{
    const int t   = blockIdx.x;
    const int tid = threadIdx.x;
    const float w0 = g_assign_w[2 * t + 0];
    const float w1 = g_assign_w[2 * t + 1];
    const float4 a = ((const float4*)(g_y + (size_t)(2 * t + 0) * DD))[tid];
    const float4 b = ((const float4*)(g_y + (size_t)(2 * t + 1) * DD))[tid];
    float4 o;
    o.x = w0 * a.x + w1 * b.x;
    o.y = w0 * a.y + w1 * b.y;
    o.z = w0 * a.z + w1 * b.z;
    o.w = w0 * a.w + w1 * b.w;
    ((float4*)(out + (size_t)t * DD))[tid] = o;
}

// ---------------------------------------------------------------------------
extern "C" void kernel_launch(void* const* d_in, const int* in_sizes, int n_in,
                              void* d_out, int out_size)
{
    const float* x      = (const float*)d_in[0];
    const float* gvec   = (const float*)d_in[1];
    const float* gate_w = (const float*)d_in[2];
    const float* w1     = (const float*)d_in[3];
    const float* w2     = (const float*)d_in[4];
    const float* w3     = (const float*)d_in[5];
    float* out = (float*)d_out;

    zero_counts_kernel<<<1, 32>>>();
    norm_router_kernel<<<NTOK, 256>>>(x, gvec, gate_w);
    mma_gemm1_kernel<<<dim3(HH / 64, NROWS / 128, EE), 256>>>(w1, w2);
    mma_gemm2_kernel<<<dim3(DD / 64, NROWS / 128, EE), 256>>>(w3);
    combine_kernel<<<NTOK, 256>>>(out);
}

// round 16
// speedup vs baseline: 1.2057x; 1.2006x over previous
#include <cuda_runtime.h>
#include <cuda_bf16.h>
#include <math.h>
#include <stdint.h>

// Problem constants
#define NTOK   2048
#define DD     1024
#define HH     2048
#define EE     8
#define NROWS  4096        // NTOK * topk(2) slot-rows

// Conflict-free smem geometry (bank-verified):
//  A planes: [8 slots][136], store col = M ^ (16*(slot>>2))
//  B planes: [8 slots][72]
#define APAD 136
#define BPAD 72

// ---------------------------------------------------------------------------
// Device scratch (static, allocation-free)
// ---------------------------------------------------------------------------
__device__ float g_xnorm[(size_t)NTOK * DD];              // 8 MB
__device__ float g_hidden[(size_t)NROWS * HH];            // 32 MB
__device__ float g_y[(size_t)NROWS * DD];                 // 16 MB
__device__ int   g_counts[EE];
__device__ int   g_rowid[EE * NROWS];
__device__ float g_assign_w[NROWS];

__global__ void zero_counts_kernel() {
    if (threadIdx.x < EE) g_counts[threadIdx.x] = 0;
}

__device__ __forceinline__ float silu_f(float v) {
    return v / (1.0f + expf(-v));
}

// mma.sync m16n8k16 bf16 + split helpers (proven R8/R9)
__device__ __forceinline__ void mma16816(float* c, const uint32_t* a, const uint32_t* b) {
    asm volatile("mma.sync.aligned.m16n8k16.row.col.f32.bf16.bf16.f32 "
                 "{%0,%1,%2,%3}, {%4,%5,%6,%7}, {%8,%9}, {%0,%1,%2,%3};"
                 : "+f"(c[0]), "+f"(c[1]), "+f"(c[2]), "+f"(c[3])
                 : "r"(a[0]), "r"(a[1]), "r"(a[2]), "r"(a[3]), "r"(b[0]), "r"(b[1]));
}
__device__ __forceinline__ void splitpack(float f0, float f1, uint32_t& hi, uint32_t& lo) {
    __nv_bfloat162 h, l;
    h.x = __float2bfloat16(f0);
    h.y = __float2bfloat16(f1);
    l.x = __float2bfloat16(f0 - __bfloat162float(h.x));
    l.y = __float2bfloat16(f1 - __bfloat162float(h.y));
    hi = *(uint32_t*)&h;
    lo = *(uint32_t*)&l;
}

// ---------------------------------------------------------------------------
// Kernel A: RMSNorm + router (proven)
// ---------------------------------------------------------------------------
__global__ void __launch_bounds__(256) norm_router_kernel(
    const float* __restrict__ x, const float* __restrict__ gvec,
    const float* __restrict__ gate_w)
{
    const int t   = blockIdx.x;
    const int tid = threadIdx.x;
    __shared__ float sh[DD];
    __shared__ float red[8];
    __shared__ float logit[EE];

    const float4 v = ((const float4*)(x + (size_t)t * DD))[tid];
    float ss = v.x*v.x + v.y*v.y + v.z*v.z + v.w*v.w;
    #pragma unroll
    for (int o = 16; o; o >>= 1) ss += __shfl_xor_sync(0xffffffffu, ss, o);
    if ((tid & 31) == 0) red[tid >> 5] = ss;
    __syncthreads();
    if (tid < 8) {
        float s = red[tid];
        #pragma unroll
        for (int o = 4; o; o >>= 1) s += __shfl_xor_sync(0xffu, s, o);
        if (tid == 0) red[0] = s;
    }
    __syncthreads();
    const float rinv = rsqrtf(red[0] * (1.0f / DD) + 1e-5f);
    const float4 gv = ((const float4*)gvec)[tid];
    float4 xn;
    xn.x = v.x * rinv * gv.x;
    xn.y = v.y * rinv * gv.y;
    xn.z = v.z * rinv * gv.z;
    xn.w = v.w * rinv * gv.w;
    ((float4*)sh)[tid] = xn;
    ((float4*)(g_xnorm + (size_t)t * DD))[tid] = xn;
    __syncthreads();

    const int w = tid >> 5, lane = tid & 31;
    float acc = 0.f;
    const float* gw = gate_w + (size_t)w * DD;
    for (int d = lane; d < DD; d += 32) acc += sh[d] * gw[d];
    #pragma unroll
    for (int o = 16; o; o >>= 1) acc += __shfl_xor_sync(0xffffffffu, acc, o);
    if (lane == 0) logit[w] = acc;
    __syncthreads();

    if (tid == 0) {
        float mx = logit[0];
        #pragma unroll
        for (int e = 1; e < EE; e++) mx = fmaxf(mx, logit[e]);
        float p[EE]; float Z = 0.f;
        #pragma unroll
        for (int e = 0; e < EE; e++) { p[e] = expf(logit[e] - mx); Z += p[e]; }
        const float iz = 1.f / Z;
        #pragma unroll
        for (int e = 0; e < EE; e++) p[e] *= iz;
        int i0 = 0;
        #pragma unroll
        for (int e = 1; e < EE; e++) if (p[e] > p[i0]) i0 = e;
        int i1 = (i0 == 0) ? 1 : 0;
        #pragma unroll
        for (int e = 0; e < EE; e++) if (e != i1 && e != i0 && p[e] > p[i1]) i1 = e;
        const float denom = p[i0] + p[i1] + 1e-10f;
        int pos0 = atomicAdd(&g_counts[i0], 1);
        g_rowid[i0 * NROWS + pos0] = t * 2 + 0;
        g_assign_w[t * 2 + 0] = p[i0] / denom;
        int pos1 = atomicAdd(&g_counts[i1], 1);
        g_rowid[i1 * NROWS + pos1] = t * 2 + 1;
        g_assign_w[t * 2 + 1] = p[i1] / denom;
    }
}

// ---------------------------------------------------------------------------
// GEMM1 (mma, 3-term split): hidden = silu(Xg@w1) * (Xg@w2)
// CTA 128M x 64N dual-B, 8 warps. R9 loaders + conflict-free swizzled smem.
// ---------------------------------------------------------------------------
__global__ void __launch_bounds__(256) mma_gemm1_kernel(
    const float* __restrict__ w1, const float* __restrict__ w2)
{
    const int e = blockIdx.z, mtb = blockIdx.y, ntb = blockIdx.x;
    const int ne = g_counts[e];
    if (mtb * 128 >= ne) return;

    __shared__ uint32_t AHi[2][8][APAD], ALo[2][8][APAD];
    __shared__ uint32_t B1Hi[2][8][BPAD], B1Lo[2][8][BPAD];
    __shared__ uint32_t B2Hi[2][8][BPAD], B2Lo[2][8][BPAD];
    __shared__ int rows[128];

    const int tid = threadIdx.x;
    if (tid < 128) {
        const int m = mtb * 128 + tid;
        rows[tid] = (m < ne) ? g_rowid[e * NROWS + m] : -1;
    }
    __syncthreads();

    // A loader: 2 threads/row (good 64B-per-row coalescing), each 8 k's
    const int arow = tid >> 1, ahalf = tid & 1;
    const int acol = arow ^ (ahalf << 4);          // swizzled store column
    const int rA = rows[arow];
    const float* aptr = (rA >= 0) ? (g_xnorm + (size_t)(rA >> 1) * DD) : g_xnorm;
    // B loader: threads 0-127 -> w1, 128-255 -> w2. Within half: kp=0..7, nq=0..15
    const int bhalf = tid >> 7;
    const int bkp = (tid & 127) >> 4, bnq = tid & 15;
    const float* bp = (bhalf == 0 ? w1 : w2) + (size_t)e * DD * HH + ntb * 64;

    float4 fa0, fa1, fb0, fb1;
    auto ldg = [&](int i) {
        const int k0 = i * 16;
        if (rA >= 0) {
            fa0 = *(const float4*)(aptr + k0 + ahalf * 8);
            fa1 = *(const float4*)(aptr + k0 + ahalf * 8 + 4);
        } else {
            fa0 = make_float4(0.f, 0.f, 0.f, 0.f);
            fa1 = fa0;
        }
        fb0 = *(const float4*)(bp + (size_t)(k0 + 2 * bkp)     * HH + bnq * 4);
        fb1 = *(const float4*)(bp + (size_t)(k0 + 2 * bkp + 1) * HH + bnq * 4);
    };
    auto sts = [&](int buf) {
        uint32_t hi, lo;
        const float fa[8] = {fa0.x, fa0.y, fa0.z, fa0.w, fa1.x, fa1.y, fa1.z, fa1.w};
        #pragma unroll
        for (int j = 0; j < 4; j++) {
            splitpack(fa[2*j], fa[2*j+1], hi, lo);
            AHi[buf][ahalf * 4 + j][acol] = hi;
            ALo[buf][ahalf * 4 + j][acol] = lo;
        }
        uint32_t h4[4], l4v[4];
        splitpack(fb0.x, fb1.x, h4[0], l4v[0]);
        splitpack(fb0.y, fb1.y, h4[1], l4v[1]);
        splitpack(fb0.z, fb1.z, h4[2], l4v[2]);
        splitpack(fb0.w, fb1.w, h4[3], l4v[3]);
        if (bhalf == 0) {
            *(uint4*)&B1Hi[buf][bkp][bnq * 4] = make_uint4(h4[0], h4[1], h4[2], h4[3]);
            *(uint4*)&B1Lo[buf][bkp][bnq * 4] = make_uint4(l4v[0], l4v[1], l4v[2], l4v[3]);
        } else {
            *(uint4*)&B2Hi[buf][bkp][bnq * 4] = make_uint4(h4[0], h4[1], h4[2], h4[3]);
            *(uint4*)&B2Lo[buf][bkp][bnq * 4] = make_uint4(l4v[0], l4v[1], l4v[2], l4v[3]);
        }
    };
    ldg(0); sts(0); __syncthreads();

    const int lane = tid & 31, wid = tid >> 5;
    const int wm = wid & 3, wn = wid >> 2;
    const int l4 = lane >> 2, lp = lane & 3;

    float acc1[2][4][4] = {};
    float acc2[2][4][4] = {};

    for (int i = 0; i < 64; i++) {
        if (i + 1 < 64) ldg(i + 1);
        const int buf = i & 1;
        uint32_t aHi[2][4], aLo[2][4];
        uint32_t b1h[4][2], b1l[4][2], b2h[4][2], b2l[4][2];
        #pragma unroll
        for (int mt = 0; mt < 2; mt++) {
            const int M0 = wm * 32 + mt * 16 + l4;
            const int M0x = M0 ^ 16;               // swizzled col for slots 4..7
            aHi[mt][0] = AHi[buf][lp][M0];         aHi[mt][1] = AHi[buf][lp][M0 + 8];
            aHi[mt][2] = AHi[buf][lp + 4][M0x];    aHi[mt][3] = AHi[buf][lp + 4][M0x + 8];
            aLo[mt][0] = ALo[buf][lp][M0];         aLo[mt][1] = ALo[buf][lp][M0 + 8];
            aLo[mt][2] = ALo[buf][lp + 4][M0x];    aLo[mt][3] = ALo[buf][lp + 4][M0x + 8];
        }
        #pragma unroll
        for (int nt = 0; nt < 4; nt++) {
            const int N0 = wn * 32 + nt * 8 + l4;
            b1h[nt][0] = B1Hi[buf][lp][N0];      b1h[nt][1] = B1Hi[buf][lp + 4][N0];
            b1l[nt][0] = B1Lo[buf][lp][N0];      b1l[nt][1] = B1Lo[buf][lp + 4][N0];
            b2h[nt][0] = B2Hi[buf][lp][N0];      b2h[nt][1] = B2Hi[buf][lp + 4][N0];
            b2l[nt][0] = B2Lo[buf][lp][N0];      b2l[nt][1] = B2Lo[buf][lp + 4][N0];
        }
        #pragma unroll
        for (int mt = 0; mt < 2; mt++) {
            #pragma unroll
            for (int nt = 0; nt < 4; nt++) {
                mma16816(acc1[mt][nt], aHi[mt], b1h[nt]);
                mma16816(acc1[mt][nt], aLo[mt], b1h[nt]);
                mma16816(acc1[mt][nt], aHi[mt], b1l[nt]);
                mma16816(acc2[mt][nt], aHi[mt], b2h[nt]);
                mma16816(acc2[mt][nt], aLo[mt], b2h[nt]);
                mma16816(acc2[mt][nt], aHi[mt], b2l[nt]);
            }
        }
        if (i + 1 < 64) sts((i + 1) & 1);
        __syncthreads();
    }

    const int hbase = ntb * 64;
    const int mrow0 = wm * 32 + l4;
    const int ncol0 = wn * 32 + 2 * lp;
    #pragma unroll
    for (int mt = 0; mt < 2; mt++) {
        #pragma unroll
        for (int h = 0; h < 2; h++) {
            const int ml = mrow0 + mt * 16 + h * 8;
            const int r = rows[ml];
            if (r < 0) continue;
            float* hrow = g_hidden + (size_t)r * HH + hbase;
            #pragma unroll
            for (int nt = 0; nt < 4; nt++) {
                const float g1a = acc1[mt][nt][2*h], g1b = acc1[mt][nt][2*h+1];
                const float g2a = acc2[mt][nt][2*h], g2b = acc2[mt][nt][2*h+1];
                float2 o;
                o.x = silu_f(g1a) * g2a;
                o.y = silu_f(g1b) * g2b;
                *(float2*)(hrow + ncol0 + nt * 8) = o;
            }
        }
    }
}

// ---------------------------------------------------------------------------
// GEMM2 (mma, 3-term split): y = hidden @ w3[e]. CTA 128M x 64N.
// R9 loaders + conflict-free swizzled smem.
// ---------------------------------------------------------------------------
__global__ void __launch_bounds__(256) mma_gemm2_kernel(const float* __restrict__ w3)
{
    const int e = blockIdx.z, mtb = blockIdx.y, ntb = blockIdx.x;
    const int ne = g_counts[e];
    if (mtb * 128 >= ne) return;

    __shared__ uint32_t AHi[2][8][APAD], ALo[2][8][APAD];
    __shared__ uint32_t BHi[2][8][BPAD], BLo[2][8][BPAD];
    __shared__ int rows[128];

    const int tid = threadIdx.x;
    if (tid < 128) {
        const int m = mtb * 128 + tid;
        rows[tid] = (m < ne) ? g_rowid[e * NROWS + m] : -1;
    }
    __syncthreads();

    const int arow = tid >> 1, ahalf = tid & 1;
    const int acol = arow ^ (ahalf << 4);
    const int rA = rows[arow];
    const float* aptr = (rA >= 0) ? (g_hidden + (size_t)rA * HH) : g_hidden;
    const int bkp = tid >> 4, bnq = tid & 15;
    const float* bp = w3 + (size_t)e * HH * DD + ntb * 64;

    float4 fa0, fa1, fb0, fb1;
    auto ldg = [&](int i) {
        const int k0 = i * 16;
        if (rA >= 0) {
            fa0 = *(const float4*)(aptr + k0 + ahalf * 8);
            fa1 = *(const float4*)(aptr + k0 + ahalf * 8 + 4);
        } else {
            fa0 = make_float4(0.f, 0.f, 0.f, 0.f);
            fa1 = fa0;
        }
        if (tid < 128) {
            fb0 = *(const float4*)(bp + (size_t)(k0 + 2 * bkp)     * DD + bnq * 4);
            fb1 = *(const float4*)(bp + (size_t)(k0 + 2 * bkp + 1) * DD + bnq * 4);
        }
    };
    auto sts = [&](int buf) {
        uint32_t hi, lo;
        const float fa[8] = {fa0.x, fa0.y, fa0.z, fa0.w, fa1.x, fa1.y, fa1.z, fa1.w};
        #pragma unroll
        for (int j = 0; j < 4; j++) {
            splitpack(fa[2*j], fa[2*j+1], hi, lo);
            AHi[buf][ahalf * 4 + j][acol] = hi;
            ALo[buf][ahalf * 4 + j][acol] = lo;
        }
        if (tid < 128) {
            uint32_t h4[4], l4v[4];
            splitpack(fb0.x, fb1.x, h4[0], l4v[0]);
            splitpack(fb0.y, fb1.y, h4[1], l4v[1]);
            splitpack(fb0.z, fb1.z, h4[2], l4v[2]);
            splitpack(fb0.w, fb1.w, h4[3], l4v[3]);
            *(uint4*)&BHi[buf][bkp][bnq * 4] = make_uint4(h4[0], h4[1], h4[2], h4[3]);
            *(uint4*)&BLo[buf][bkp][bnq * 4] = make_uint4(l4v[0], l4v[1], l4v[2], l4v[3]);
        }
    };
    ldg(0); sts(0); __syncthreads();

    const int lane = tid & 31, wid = tid >> 5;
    const int wm = wid & 3, wn = wid >> 2;
    const int l4 = lane >> 2, lp = lane & 3;

    float acc[2][4][4] = {};

    for (int i = 0; i < 128; i++) {
        if (i + 1 < 128) ldg(i + 1);
        const int buf = i & 1;
        uint32_t aHi[2][4], aLo[2][4], bHi[4][2], bLo[4][2];
        #pragma unroll
        for (int mt = 0; mt < 2; mt++) {
            const int M0 = wm * 32 + mt * 16 + l4;
            const int M0x = M0 ^ 16;
            aHi[mt][0] = AHi[buf][lp][M0];         aHi[mt][1] = AHi[buf][lp][M0 + 8];
            aHi[mt][2] = AHi[buf][lp + 4][M0x];    aHi[mt][3] = AHi[buf][lp + 4][M0x + 8];
            aLo[mt][0] = ALo[buf][lp][M0];         aLo[mt][1] = ALo[buf][lp][M0 + 8];
            aLo[mt][2] = ALo[buf][lp + 4][M0x];    aLo[mt][3] = ALo[buf][lp + 4][M0x + 8];
        }
        #pragma unroll
        for (int nt = 0; nt < 4; nt++) {
            const int N0 = wn * 32 + nt * 8 + l4;
            bHi[nt][0] = BHi[buf][lp][N0];       bHi[nt][1] = BHi[buf][lp + 4][N0];
            bLo[nt][0] = BLo[buf][lp][N0];       bLo[nt][1] = BLo[buf][lp + 4][N0];
        }
        #pragma unroll
        for (int mt = 0; mt < 2; mt++) {
            #pragma unroll
            for (int nt = 0; nt < 4; nt++) {
                mma16816(acc[mt][nt], aHi[mt], bHi[nt]);
                mma16816(acc[mt][nt], aLo[mt], bHi[nt]);
                mma16816(acc[mt][nt], aHi[mt], bLo[nt]);
            }
        }
        if (i + 1 < 128) sts((i + 1) & 1);
        __syncthreads();
    }

    const int dbase = ntb * 64;
    const int mrow0 = wm * 32 + l4;
    const int ncol0 = wn * 32 + 2 * lp;
    #pragma unroll
    for (int mt = 0; mt < 2; mt++) {
        #pragma unroll
        for (int h = 0; h < 2; h++) {
            const int ml = mrow0 + mt * 16 + h * 8;
            const int r = rows[ml];
            if (r < 0) continue;
            float* yrow = g_y + (size_t)r * DD + dbase;
            #pragma unroll
            for (int nt = 0; nt < 4; nt++) {
                float2 o;
                o.x = acc[mt][nt][2*h];
                o.y = acc[mt][nt][2*h+1];
                *(float2*)(yrow + ncol0 + nt * 8) = o;
            }
        }
    }
}

// ---------------------------------------------------------------------------
// Kernel D: combine out[t] = w0*y[2t] + w1*y[2t+1]
// ---------------------------------------------------------------------------
__global__ void __launch_bounds__(256) combine_kernel(float* __restrict__ out)
{
    const int t   = blockIdx.x;
    const int tid = threadIdx.x;
    const float w0 = g_assign_w[2 * t + 0];
    const float w1 = g_assign_w[2 * t + 1];
    const float4 a = ((const float4*)(g_y + (size_t)(2 * t + 0) * DD))[tid];
    const float4 b = ((const float4*)(g_y + (size_t)(2 * t + 1) * DD))[tid];
    float4 o;
    o.x = w0 * a.x + w1 * b.x;
    o.y = w0 * a.y + w1 * b.y;
    o.z = w0 * a.z + w1 * b.z;
    o.w = w0 * a.w + w1 * b.w;
    ((float4*)(out + (size_t)t * DD))[tid] = o;
}

// ---------------------------------------------------------------------------
extern "C" void kernel_launch(void* const* d_in, const int* in_sizes, int n_in,
                              void* d_out, int out_size)
{
    const float* x      = (const float*)d_in[0];
    const float* gvec   = (const float*)d_in[1];
    const float* gate_w = (const float*)d_in[2];
    const float* w1     = (const float*)d_in[3];
    const float* w2     = (const float*)d_in[4];
    const float* w3     = (const float*)d_in[5];
    float* out = (float*)d_out;

    zero_counts_kernel<<<1, 32>>>();
    norm_router_kernel<<<NTOK, 256>>>(x, gvec, gate_w);
    mma_gemm1_kernel<<<dim3(HH / 64, NROWS / 128, EE), 256>>>(w1, w2);
    mma_gemm2_kernel<<<dim3(DD / 64, NROWS / 128, EE), 256>>>(w3);
    combine_kernel<<<NTOK, 256>>>(out);
}

// round 17
// speedup vs baseline: 1.2300x; 1.0202x over previous
#include <cuda_runtime.h>
#include <cuda_bf16.h>
#include <math.h>
#include <stdint.h>

// Problem constants
#define NTOK   2048
#define DD     1024
#define HH     2048
#define EE     8
#define NROWS  4096        // NTOK * topk(2) slot-rows

// Conflict-free smem geometry (bank-verified, proven R16):
//  A planes: [8 slots][136], store col = M ^ (16*(slot>>2))
//  B planes: [8 slots][72]
#define APAD 136
#define BPAD 72

// ---------------------------------------------------------------------------
// Device scratch (static, allocation-free)
// Activations stored as k-paired bf16x2 hi/lo planes (uint32 per k-pair).
// ---------------------------------------------------------------------------
__device__ uint32_t g_xa_hi[(size_t)NTOK * 512];          // 4 MB
__device__ uint32_t g_xa_lo[(size_t)NTOK * 512];          // 4 MB
__device__ uint32_t g_ha_hi[(size_t)NROWS * 1024];        // 16 MB
__device__ uint32_t g_ha_lo[(size_t)NROWS * 1024];        // 16 MB
__device__ float g_y[(size_t)NROWS * DD];                 // 16 MB
__device__ int   g_counts[EE];
__device__ int   g_rowid[EE * NROWS];
__device__ float g_assign_w[NROWS];

__global__ void zero_counts_kernel() {
    if (threadIdx.x < EE) g_counts[threadIdx.x] = 0;
}

__device__ __forceinline__ float silu_f(float v) {
    return v / (1.0f + expf(-v));
}

// mma.sync m16n8k16 bf16 + split helpers (proven R8/R9/R16)
__device__ __forceinline__ void mma16816(float* c, const uint32_t* a, const uint32_t* b) {
    asm volatile("mma.sync.aligned.m16n8k16.row.col.f32.bf16.bf16.f32 "
                 "{%0,%1,%2,%3}, {%4,%5,%6,%7}, {%8,%9}, {%0,%1,%2,%3};"
                 : "+f"(c[0]), "+f"(c[1]), "+f"(c[2]), "+f"(c[3])
                 : "r"(a[0]), "r"(a[1]), "r"(a[2]), "r"(a[3]), "r"(b[0]), "r"(b[1]));
}
__device__ __forceinline__ void splitpack(float f0, float f1, uint32_t& hi, uint32_t& lo) {
    __nv_bfloat162 h, l;
    h.x = __float2bfloat16(f0);
    h.y = __float2bfloat16(f1);
    l.x = __float2bfloat16(f0 - __bfloat162float(h.x));
    l.y = __float2bfloat16(f1 - __bfloat162float(h.y));
    hi = *(uint32_t*)&h;
    lo = *(uint32_t*)&l;
}

// ---------------------------------------------------------------------------
// Kernel A: RMSNorm + router; writes k-paired hi/lo planes of x_norm
// ---------------------------------------------------------------------------
__global__ void __launch_bounds__(256) norm_router_kernel(
    const float* __restrict__ x, const float* __restrict__ gvec,
    const float* __restrict__ gate_w)
{
    const int t   = blockIdx.x;
    const int tid = threadIdx.x;
    __shared__ float sh[DD];
    __shared__ float red[8];
    __shared__ float logit[EE];

    const float4 v = ((const float4*)(x + (size_t)t * DD))[tid];
    float ss = v.x*v.x + v.y*v.y + v.z*v.z + v.w*v.w;
    #pragma unroll
    for (int o = 16; o; o >>= 1) ss += __shfl_xor_sync(0xffffffffu, ss, o);
    if ((tid & 31) == 0) red[tid >> 5] = ss;
    __syncthreads();
    if (tid < 8) {
        float s = red[tid];
        #pragma unroll
        for (int o = 4; o; o >>= 1) s += __shfl_xor_sync(0xffu, s, o);
        if (tid == 0) red[0] = s;
    }
    __syncthreads();
    const float rinv = rsqrtf(red[0] * (1.0f / DD) + 1e-5f);
    const float4 gv = ((const float4*)gvec)[tid];
    float4 xn;
    xn.x = v.x * rinv * gv.x;
    xn.y = v.y * rinv * gv.y;
    xn.z = v.z * rinv * gv.z;
    xn.w = v.w * rinv * gv.w;
    ((float4*)sh)[tid] = xn;

    uint32_t h0, l0, h1, l1;
    splitpack(xn.x, xn.y, h0, l0);
    splitpack(xn.z, xn.w, h1, l1);
    ((uint2*)(g_xa_hi + (size_t)t * 512))[tid] = make_uint2(h0, h1);
    ((uint2*)(g_xa_lo + (size_t)t * 512))[tid] = make_uint2(l0, l1);
    __syncthreads();

    const int w = tid >> 5, lane = tid & 31;
    float acc = 0.f;
    const float* gw = gate_w + (size_t)w * DD;
    for (int d = lane; d < DD; d += 32) acc += sh[d] * gw[d];
    #pragma unroll
    for (int o = 16; o; o >>= 1) acc += __shfl_xor_sync(0xffffffffu, acc, o);
    if (lane == 0) logit[w] = acc;
    __syncthreads();

    if (tid == 0) {
        float mx = logit[0];
        #pragma unroll
        for (int e = 1; e < EE; e++) mx = fmaxf(mx, logit[e]);
        float p[EE]; float Z = 0.f;
        #pragma unroll
        for (int e = 0; e < EE; e++) { p[e] = expf(logit[e] - mx); Z += p[e]; }
        const float iz = 1.f / Z;
        #pragma unroll
        for (int e = 0; e < EE; e++) p[e] *= iz;
        int i0 = 0;
        #pragma unroll
        for (int e = 1; e < EE; e++) if (p[e] > p[i0]) i0 = e;
        int i1 = (i0 == 0) ? 1 : 0;
        #pragma unroll
        for (int e = 0; e < EE; e++) if (e != i1 && e != i0 && p[e] > p[i1]) i1 = e;
        const float denom = p[i0] + p[i1] + 1e-10f;
        int pos0 = atomicAdd(&g_counts[i0], 1);
        g_rowid[i0 * NROWS + pos0] = t * 2 + 0;
        g_assign_w[t * 2 + 0] = p[i0] / denom;
        int pos1 = atomicAdd(&g_counts[i1], 1);
        g_rowid[i1 * NROWS + pos1] = t * 2 + 1;
        g_assign_w[t * 2 + 1] = p[i1] / denom;
    }
}

// ---------------------------------------------------------------------------
// GEMM1 (mma, 3-term split): hidden = silu(Xg@w1) * (Xg@w2)
// CTA 128M x 64N dual-B, 8 warps. A: pure uint4 copy from pre-split planes.
// B: in-kernel splitpack (proven). Conflict-free swizzled smem (R16).
// ---------------------------------------------------------------------------
__global__ void __launch_bounds__(256) mma_gemm1_kernel(
    const float* __restrict__ w1, const float* __restrict__ w2)
{
    const int e = blockIdx.z, mtb = blockIdx.y, ntb = blockIdx.x;
    const int ne = g_counts[e];
    if (mtb * 128 >= ne) return;

    __shared__ uint32_t AHi[2][8][APAD], ALo[2][8][APAD];
    __shared__ uint32_t B1Hi[2][8][BPAD], B1Lo[2][8][BPAD];
    __shared__ uint32_t B2Hi[2][8][BPAD], B2Lo[2][8][BPAD];
    __shared__ int rows[128];

    const int tid = threadIdx.x;
    if (tid < 128) {
        const int m = mtb * 128 + tid;
        rows[tid] = (m < ne) ? g_rowid[e * NROWS + m] : -1;
    }
    __syncthreads();

    // A loader: 2 threads/row, each 4 k-pairs (= 8 k's); pure copy
    const int arow = tid >> 1, ahalf = tid & 1;
    const int acol = arow ^ (ahalf << 4);          // swizzled store column
    const int rA = rows[arow];
    const uint32_t* ahip = g_xa_hi + (size_t)(rA >> 1) * 512;
    const uint32_t* alop = g_xa_lo + (size_t)(rA >> 1) * 512;
    // B loader: threads 0-127 -> w1, 128-255 -> w2. Within half: kp=0..7, nq=0..15
    const int bhalf = tid >> 7;
    const int bkp = (tid & 127) >> 4, bnq = tid & 15;
    const float* bp = (bhalf == 0 ? w1 : w2) + (size_t)e * DD * HH + ntb * 64;

    uint4 fha, fla;
    float4 fb0, fb1;
    auto ldg = [&](int i) {
        const int kp0 = i * 8 + ahalf * 4;         // pair index
        if (rA >= 0) {
            fha = *(const uint4*)(ahip + kp0);
            fla = *(const uint4*)(alop + kp0);
        } else {
            fha = make_uint4(0u, 0u, 0u, 0u);
            fla = fha;
        }
        const int k0 = i * 16;
        fb0 = *(const float4*)(bp + (size_t)(k0 + 2 * bkp)     * HH + bnq * 4);
        fb1 = *(const float4*)(bp + (size_t)(k0 + 2 * bkp + 1) * HH + bnq * 4);
    };
    auto sts = [&](int buf) {
        const uint32_t ah[4] = {fha.x, fha.y, fha.z, fha.w};
        const uint32_t al[4] = {fla.x, fla.y, fla.z, fla.w};
        #pragma unroll
        for (int j = 0; j < 4; j++) {
            AHi[buf][ahalf * 4 + j][acol] = ah[j];
            ALo[buf][ahalf * 4 + j][acol] = al[j];
        }
        uint32_t h4[4], l4v[4];
        splitpack(fb0.x, fb1.x, h4[0], l4v[0]);
        splitpack(fb0.y, fb1.y, h4[1], l4v[1]);
        splitpack(fb0.z, fb1.z, h4[2], l4v[2]);
        splitpack(fb0.w, fb1.w, h4[3], l4v[3]);
        if (bhalf == 0) {
            *(uint4*)&B1Hi[buf][bkp][bnq * 4] = make_uint4(h4[0], h4[1], h4[2], h4[3]);
            *(uint4*)&B1Lo[buf][bkp][bnq * 4] = make_uint4(l4v[0], l4v[1], l4v[2], l4v[3]);
        } else {
            *(uint4*)&B2Hi[buf][bkp][bnq * 4] = make_uint4(h4[0], h4[1], h4[2], h4[3]);
            *(uint4*)&B2Lo[buf][bkp][bnq * 4] = make_uint4(l4v[0], l4v[1], l4v[2], l4v[3]);
        }
    };
    ldg(0); sts(0); __syncthreads();

    const int lane = tid & 31, wid = tid >> 5;
    const int wm = wid & 3, wn = wid >> 2;
    const int l4 = lane >> 2, lp = lane & 3;

    float acc1[2][4][4] = {};
    float acc2[2][4][4] = {};

    for (int i = 0; i < 64; i++) {
        if (i + 1 < 64) ldg(i + 1);
        const int buf = i & 1;
        uint32_t aHi[2][4], aLo[2][4];
        uint32_t b1h[4][2], b1l[4][2], b2h[4][2], b2l[4][2];
        #pragma unroll
        for (int mt = 0; mt < 2; mt++) {
            const int M0 = wm * 32 + mt * 16 + l4;
            const int M0x = M0 ^ 16;               // swizzled col for slots 4..7
            aHi[mt][0] = AHi[buf][lp][M0];         aHi[mt][1] = AHi[buf][lp][M0 + 8];
            aHi[mt][2] = AHi[buf][lp + 4][M0x];    aHi[mt][3] = AHi[buf][lp + 4][M0x + 8];
            aLo[mt][0] = ALo[buf][lp][M0];         aLo[mt][1] = ALo[buf][lp][M0 + 8];
            aLo[mt][2] = ALo[buf][lp + 4][M0x];    aLo[mt][3] = ALo[buf][lp + 4][M0x + 8];
        }
        #pragma unroll
        for (int nt = 0; nt < 4; nt++) {
            const int N0 = wn * 32 + nt * 8 + l4;
            b1h[nt][0] = B1Hi[buf][lp][N0];      b1h[nt][1] = B1Hi[buf][lp + 4][N0];
            b1l[nt][0] = B1Lo[buf][lp][N0];      b1l[nt][1] = B1Lo[buf][lp + 4][N0];
            b2h[nt][0] = B2Hi[buf][lp][N0];      b2h[nt][1] = B2Hi[buf][lp + 4][N0];
            b2l[nt][0] = B2Lo[buf][lp][N0];      b2l[nt][1] = B2Lo[buf][lp + 4][N0];
        }
        #pragma unroll
        for (int mt = 0; mt < 2; mt++) {
            #pragma unroll
            for (int nt = 0; nt < 4; nt++) {
                mma16816(acc1[mt][nt], aHi[mt], b1h[nt]);
                mma16816(acc1[mt][nt], aLo[mt], b1h[nt]);
                mma16816(acc1[mt][nt], aHi[mt], b1l[nt]);
                mma16816(acc2[mt][nt], aHi[mt], b2h[nt]);
                mma16816(acc2[mt][nt], aLo[mt], b2h[nt]);
                mma16816(acc2[mt][nt], aHi[mt], b2l[nt]);
            }
        }
        if (i + 1 < 64) sts((i + 1) & 1);
        __syncthreads();
    }

    // Epilogue: silu(h1)*h2 -> k-paired hi/lo planes of hidden
    const int hbase = ntb * 64;
    const int mrow0 = wm * 32 + l4;
    const int ncol0 = wn * 32 + 2 * lp;
    #pragma unroll
    for (int mt = 0; mt < 2; mt++) {
        #pragma unroll
        for (int h = 0; h < 2; h++) {
            const int ml = mrow0 + mt * 16 + h * 8;
            const int r = rows[ml];
            if (r < 0) continue;
            uint32_t* hhi = g_ha_hi + (size_t)r * 1024;
            uint32_t* hlo = g_ha_lo + (size_t)r * 1024;
            #pragma unroll
            for (int nt = 0; nt < 4; nt++) {
                const float g1a = acc1[mt][nt][2*h], g1b = acc1[mt][nt][2*h+1];
                const float g2a = acc2[mt][nt][2*h], g2b = acc2[mt][nt][2*h+1];
                const float va = silu_f(g1a) * g2a;
                const float vb = silu_f(g1b) * g2b;
                uint32_t hi, lo;
                splitpack(va, vb, hi, lo);
                const int pidx = (hbase + ncol0 + nt * 8) >> 1;
                hhi[pidx] = hi;
                hlo[pidx] = lo;
            }
        }
    }
}

// ---------------------------------------------------------------------------
// GEMM2 (mma, 3-term split): y = hidden @ w3[e]. CTA 128M x 64N.
// A: pure uint4 copy from pre-split hidden planes. B: in-kernel splitpack.
// ---------------------------------------------------------------------------
__global__ void __launch_bounds__(256) mma_gemm2_kernel(const float* __restrict__ w3)
{
    const int e = blockIdx.z, mtb = blockIdx.y, ntb = blockIdx.x;
    const int ne = g_counts[e];
    if (mtb * 128 >= ne) return;

    __shared__ uint32_t AHi[2][8][APAD], ALo[2][8][APAD];
    __shared__ uint32_t BHi[2][8][BPAD], BLo[2][8][BPAD];
    __shared__ int rows[128];

    const int tid = threadIdx.x;
    if (tid < 128) {
        const int m = mtb * 128 + tid;
        rows[tid] = (m < ne) ? g_rowid[e * NROWS + m] : -1;
    }
    __syncthreads();

    const int arow = tid >> 1, ahalf = tid & 1;
    const int acol = arow ^ (ahalf << 4);
    const int rA = rows[arow];
    const uint32_t* ahip = g_ha_hi + (size_t)rA * 1024;
    const uint32_t* alop = g_ha_lo + (size_t)rA * 1024;
    const int bkp = tid >> 4, bnq = tid & 15;
    const float* bp = w3 + (size_t)e * HH * DD + ntb * 64;

    uint4 fha, fla;
    float4 fb0, fb1;
    auto ldg = [&](int i) {
        const int kp0 = i * 8 + ahalf * 4;
        if (rA >= 0) {
            fha = *(const uint4*)(ahip + kp0);
            fla = *(const uint4*)(alop + kp0);
        } else {
            fha = make_uint4(0u, 0u, 0u, 0u);
            fla = fha;
        }
        if (tid < 128) {
            const int k0 = i * 16;
            fb0 = *(const float4*)(bp + (size_t)(k0 + 2 * bkp)     * DD + bnq * 4);
            fb1 = *(const float4*)(bp + (size_t)(k0 + 2 * bkp + 1) * DD + bnq * 4);
        }
    };
    auto sts = [&](int buf) {
        const uint32_t ah[4] = {fha.x, fha.y, fha.z, fha.w};
        const uint32_t al[4] = {fla.x, fla.y, fla.z, fla.w};
        #pragma unroll
        for (int j = 0; j < 4; j++) {
            AHi[buf][ahalf * 4 + j][acol] = ah[j];
            ALo[buf][ahalf * 4 + j][acol] = al[j];
        }
        if (tid < 128) {
            uint32_t h4[4], l4v[4];
            splitpack(fb0.x, fb1.x, h4[0], l4v[0]);
            splitpack(fb0.y, fb1.y, h4[1], l4v[1]);
            splitpack(fb0.z, fb1.z, h4[2], l4v[2]);
            splitpack(fb0.w, fb1.w, h4[3], l4v[3]);
            *(uint4*)&BHi[buf][bkp][bnq * 4] = make_uint4(h4[0], h4[1], h4[2], h4[3]);
            *(uint4*)&BLo[buf][bkp][bnq * 4] = make_uint4(l4v[0], l4v[1], l4v[2], l4v[3]);
        }
    };
    ldg(0); sts(0); __syncthreads();

    const int lane = tid & 31, wid = tid >> 5;
    const int wm = wid & 3, wn = wid >> 2;
    const int l4 = lane >> 2, lp = lane & 3;

    float acc[2][4][4] = {};

    for (int i = 0; i < 128; i++) {
        if (i + 1 < 128) ldg(i + 1);
        const int buf = i & 1;
        uint32_t aHi[2][4], aLo[2][4], bHi[4][2], bLo[4][2];
        #pragma unroll
        for (int mt = 0; mt < 2; mt++) {
            const int M0 = wm * 32 + mt * 16 + l4;
            const int M0x = M0 ^ 16;
            aHi[mt][0] = AHi[buf][lp][M0];         aHi[mt][1] = AHi[buf][lp][M0 + 8];
            aHi[mt][2] = AHi[buf][lp + 4][M0x];    aHi[mt][3] = AHi[buf][lp + 4][M0x + 8];
            aLo[mt][0] = ALo[buf][lp][M0];         aLo[mt][1] = ALo[buf][lp][M0 + 8];
            aLo[mt][2] = ALo[buf][lp + 4][M0x];    aLo[mt][3] = ALo[buf][lp + 4][M0x + 8];
        }
        #pragma unroll
        for (int nt = 0; nt < 4; nt++) {
            const int N0 = wn * 32 + nt * 8 + l4;
            bHi[nt][0] = BHi[buf][lp][N0];       bHi[nt][1] = BHi[buf][lp + 4][N0];
            bLo[nt][0] = BLo[buf][lp][N0];       bLo[nt][1] = BLo[buf][lp + 4][N0];
        }
        #pragma unroll
        for (int mt = 0; mt < 2; mt++) {
            #pragma unroll
            for (int nt = 0; nt < 4; nt++) {
                mma16816(acc[mt][nt], aHi[mt], bHi[nt]);
                mma16816(acc[mt][nt], aLo[mt], bHi[nt]);
                mma16816(acc[mt][nt], aHi[mt], bLo[nt]);
            }
        }
        if (i + 1 < 128) sts((i + 1) & 1);
        __syncthreads();
    }

    const int dbase = ntb * 64;
    const int mrow0 = wm * 32 + l4;
    const int ncol0 = wn * 32 + 2 * lp;
    #pragma unroll
    for (int mt = 0; mt < 2; mt++) {
        #pragma unroll
        for (int h = 0; h < 2; h++) {
            const int ml = mrow0 + mt * 16 + h * 8;
            const int r = rows[ml];
            if (r < 0) continue;
            float* yrow = g_y + (size_t)r * DD + dbase;
            #pragma unroll
            for (int nt = 0; nt < 4; nt++) {
                float2 o;
                o.x = acc[mt][nt][2*h];
                o.y = acc[mt][nt][2*h+1];
                *(float2*)(yrow + ncol0 + nt * 8) = o;
            }
        }
    }
}

// ---------------------------------------------------------------------------
// Kernel D: combine out[t] = w0*y[2t] + w1*y[2t+1]
// ---------------------------------------------------------------------------
__global__ void __launch_bounds__(256) combine_kernel(float* __restrict__ out)
{
    const int t   = blockIdx.x;
    const int tid = threadIdx.x;
    const float w0 = g_assign_w[2 * t + 0];
    const float w1 = g_assign_w[2 * t + 1];
    const float4 a = ((const float4*)(g_y + (size_t)(2 * t + 0) * DD))[tid];
    const float4 b = ((const float4*)(g_y + (size_t)(2 * t + 1) * DD))[tid];
    float4 o;
    o.x = w0 * a.x + w1 * b.x;
    o.y = w0 * a.y + w1 * b.y;
    o.z = w0 * a.z + w1 * b.z;
    o.w = w0 * a.w + w1 * b.w;
    ((float4*)(out + (size_t)t * DD))[tid] = o;
}

// ---------------------------------------------------------------------------
extern "C" void kernel_launch(void* const* d_in, const int* in_sizes, int n_in,
                              void* d_out, int out_size)
{
    const float* x      = (const float*)d_in[0];
    const float* gvec   = (const float*)d_in[1];
    const float* gate_w = (const float*)d_in[2];
    const float* w1     = (const float*)d_in[3];
    const float* w2     = (const float*)d_in[4];
    const float* w3     = (const float*)d_in[5];
    float* out = (float*)d_out;

    zero_counts_kernel<<<1, 32>>>();
    norm_router_kernel<<<NTOK, 256>>>(x, gvec, gate_w);
    mma_gemm1_kernel<<<dim3(HH / 64, NROWS / 128, EE), 256>>>(w1, w2);
    mma_gemm2_kernel<<<dim3(DD / 64, NROWS / 128, EE), 256>>>(w3);
    combine_kernel<<<NTOK, 256>>>(out);
}